// round 7
// baseline (speedup 1.0000x reference)
#include <cuda_runtime.h>
#include <cstdint>

// Fused attention with softmax over the HEAD axis (dim=1 quirk).
// B=2, H=8, S=4096, d=64. fp32 end-to-end SIMT baseline.
//
// Layout notes:
//  Q: [B,H,S,64]   K: [B,H,64,S] (pre-transposed)   V: [B,H,S,64]
//  Output reshape in the reference is a RAW reshape of [B,H,S,d], so we
//  write O in [B,H,S,64] contiguous order directly.
//
// Per CTA: one (b, 32-query block), all 8 heads. 512 threads = 16 warps;
// warp w handles head (w>>1), s-half (w&1). Loop over 32-key tiles:
//   1. stage K[8][64][32] and V[8][32][64] tiles in smem
//   2. E[h][s][t] = (Q*scale) @ K  (register micro-tile 2s x 8t per lane)
//   3. softmax over h in smem (local per (s,t) -- no running state needed)
//   4. O[h][s][:] += A @ V  (register micro-tile 2s x 16dv per lane)

namespace {
constexpr int NB = 2, NH = 8, SEQ = 4096, D = 64;
constexpr int S_TILE = 32, T_TILE = 32;
constexpr int ES_LD  = 34;      // padded score-row stride (8B-aligned, bank-spread)
constexpr int THREADS = 512;
constexpr int SMEM_FLOATS = NH*D*S_TILE      // Qs (k-major, scaled)
                          + NH*D*T_TILE      // Ks
                          + NH*T_TILE*D      // Vs
                          + NH*S_TILE*ES_LD; // Es (scores -> weights in place)
constexpr int SMEM_BYTES = SMEM_FLOATS * 4;  // 231424 B <= 232448 B cap
}

__global__ __launch_bounds__(THREADS, 1)
void attn_headsoftmax_kernel(const float* __restrict__ Q,
                             const float* __restrict__ K,
                             const float* __restrict__ V,
                             float* __restrict__ O)
{
    extern __shared__ float smem[];
    float* Qs = smem;                   // [NH][D][S_TILE]  (k-major, s contiguous)
    float* Ks = Qs + NH*D*S_TILE;       // [NH][D][T_TILE]  (k-major, t contiguous)
    float* Vs = Ks + NH*D*T_TILE;       // [NH][T_TILE][D]
    float* Es = Vs + NH*T_TILE*D;       // [NH][S_TILE][ES_LD]

    const int tid  = threadIdx.x;
    const int wid  = tid >> 5;
    const int lane = tid & 31;
    const int b    = blockIdx.x >> 7;             // 128 s-blocks per batch
    const int s0   = (blockIdx.x & 127) * S_TILE;

    const int h     = wid >> 1;                   // warp's head
    const int sbase = (wid & 1) * 16;             // warp's s-half within tile
    const int sg    = lane >> 2;                  // 8 s-groups
    const int tg    = lane & 3;                   // 4 t/dv-groups
    const int sA    = sbase + sg * 2;             // lane's first of 2 s rows

    const float scale = 0.044194173824159216f;    // 1/sqrt(512)

    // ---- stage Q tile once: scaled + transposed to [h][k][s] ----
    {
        const int r    = tid >> 1;                // 0..255 == h*32 + s
        const int half = tid & 1;                 // which 32-wide k half
        const int qh = r >> 5, qs = r & 31;
        const float* src = Q + (((size_t)(b*NH + qh))*SEQ + (size_t)(s0 + qs))*D + half*32;
        #pragma unroll
        for (int m = 0; m < 8; ++m) {
            float4 v = *(const float4*)(src + m*4);
            const int k0 = half*32 + m*4;
            Qs[(qh*D + k0+0)*S_TILE + qs] = v.x * scale;
            Qs[(qh*D + k0+1)*S_TILE + qs] = v.y * scale;
            Qs[(qh*D + k0+2)*S_TILE + qs] = v.z * scale;
            Qs[(qh*D + k0+3)*S_TILE + qs] = v.w * scale;
        }
    }

    float oacc[2][16];                            // lane's O accumulator: 2s x 16dv
    #pragma unroll
    for (int i = 0; i < 2; ++i)
        #pragma unroll
        for (int j = 0; j < 16; ++j) oacc[i][j] = 0.f;

    const size_t kb = ((size_t)b * NH * D) * SEQ; // base of this batch's K rows

    for (int t0g = 0; t0g < SEQ; t0g += T_TILE) {
        __syncthreads();  // previous tile fully consumed (and Qs visible on iter 0)

        // ---- stage K tile: 512 rows (h*64+k) x 32 t, coalesced float4 ----
        #pragma unroll
        for (int i = 0; i < 8; ++i) {
            const int f   = tid + i*THREADS;      // 0..4095 float4s
            const int row = f >> 3;               // h*64 + k
            const int seg = (f & 7) * 4;
            float4 v = *(const float4*)(K + kb + (size_t)row*SEQ + t0g + seg);
            *(float4*)&Ks[row*T_TILE + seg] = v;
        }
        // ---- stage V tile: 256 rows (h*32+t) x 64 dv ----
        #pragma unroll
        for (int i = 0; i < 8; ++i) {
            const int f   = tid + i*THREADS;
            const int row = f >> 4;               // h*32 + t
            const int col = (f & 15) * 4;
            const int vh = row >> 5, vt = row & 31;
            float4 v = *(const float4*)(V + (((size_t)(b*NH + vh))*SEQ + (size_t)(t0g + vt))*D + col);
            *(float4*)&Vs[row*D + col] = v;
        }
        __syncthreads();

        // ---- E[h][s][t] = (Q*scale) @ K : per-lane 2s x 8t micro-tile ----
        {
            float e0[8], e1[8];
            #pragma unroll
            for (int j = 0; j < 8; ++j) { e0[j] = 0.f; e1[j] = 0.f; }
            const float* qb  = Qs + h*D*S_TILE + sA;
            const float* kbp = Ks + h*D*T_TILE + tg*8;
            #pragma unroll 8
            for (int k = 0; k < D; ++k) {
                float2 q  = *(const float2*)(qb  + k*S_TILE);
                float4 b0 = *(const float4*)(kbp + k*T_TILE);
                float4 b1 = *(const float4*)(kbp + k*T_TILE + 4);
                e0[0] += q.x*b0.x; e0[1] += q.x*b0.y; e0[2] += q.x*b0.z; e0[3] += q.x*b0.w;
                e0[4] += q.x*b1.x; e0[5] += q.x*b1.y; e0[6] += q.x*b1.z; e0[7] += q.x*b1.w;
                e1[0] += q.y*b0.x; e1[1] += q.y*b0.y; e1[2] += q.y*b0.z; e1[3] += q.y*b0.w;
                e1[4] += q.y*b1.x; e1[5] += q.y*b1.y; e1[6] += q.y*b1.z; e1[7] += q.y*b1.w;
            }
            float* eb = Es + (h*S_TILE + sA)*ES_LD + tg*8;
            *(float2*)(eb+0) = make_float2(e0[0], e0[1]);
            *(float2*)(eb+2) = make_float2(e0[2], e0[3]);
            *(float2*)(eb+4) = make_float2(e0[4], e0[5]);
            *(float2*)(eb+6) = make_float2(e0[6], e0[7]);
            float* eb1 = eb + ES_LD;
            *(float2*)(eb1+0) = make_float2(e1[0], e1[1]);
            *(float2*)(eb1+2) = make_float2(e1[2], e1[3]);
            *(float2*)(eb1+4) = make_float2(e1[4], e1[5]);
            *(float2*)(eb1+6) = make_float2(e1[6], e1[7]);
        }
        __syncthreads();

        // ---- softmax over the 8 heads, in place (local per (s,t)) ----
        {
            const int ss = tid >> 4;              // s in 0..31
            const int tt = (tid & 15) * 2;        // pair of t positions
            float2 ev[8];
            #pragma unroll
            for (int hh = 0; hh < 8; ++hh)
                ev[hh] = *(const float2*)&Es[(hh*S_TILE + ss)*ES_LD + tt];
            float m0 = ev[0].x, m1 = ev[0].y;
            #pragma unroll
            for (int hh = 1; hh < 8; ++hh) { m0 = fmaxf(m0, ev[hh].x); m1 = fmaxf(m1, ev[hh].y); }
            float sum0 = 0.f, sum1 = 0.f;
            #pragma unroll
            for (int hh = 0; hh < 8; ++hh) {
                ev[hh].x = __expf(ev[hh].x - m0);
                ev[hh].y = __expf(ev[hh].y - m1);
                sum0 += ev[hh].x; sum1 += ev[hh].y;
            }
            const float r0 = __fdividef(1.f, sum0);
            const float r1 = __fdividef(1.f, sum1);
            #pragma unroll
            for (int hh = 0; hh < 8; ++hh)
                *(float2*)&Es[(hh*S_TILE + ss)*ES_LD + tt] =
                    make_float2(ev[hh].x * r0, ev[hh].y * r1);
        }
        __syncthreads();

        // ---- O += A @ V : per-lane 2s x 16dv micro-tile (dv = tg*4 + 16j + r) ----
        {
            const float* ab0 = Es + (h*S_TILE + sA)*ES_LD;
            const float* ab1 = ab0 + ES_LD;
            const float* vb  = Vs + h*T_TILE*D + tg*4;
            #pragma unroll 4
            for (int t = 0; t < T_TILE; ++t) {
                const float a0 = ab0[t];
                const float a1 = ab1[t];
                const float* vr = vb + t*D;
                #pragma unroll
                for (int j = 0; j < 4; ++j) {
                    float4 v = *(const float4*)(vr + j*16);
                    oacc[0][j*4+0] += a0*v.x; oacc[0][j*4+1] += a0*v.y;
                    oacc[0][j*4+2] += a0*v.z; oacc[0][j*4+3] += a0*v.w;
                    oacc[1][j*4+0] += a1*v.x; oacc[1][j*4+1] += a1*v.y;
                    oacc[1][j*4+2] += a1*v.z; oacc[1][j*4+3] += a1*v.w;
                }
            }
        }
    }

    // ---- writeback: raw [B,H,S,64] order == reference's .reshape view ----
    #pragma unroll
    for (int i = 0; i < 2; ++i) {
        float* dst = O + (((size_t)(b*NH + h))*SEQ + (size_t)(s0 + sA + i))*D + tg*4;
        #pragma unroll
        for (int j = 0; j < 4; ++j)
            *(float4*)(dst + j*16) = make_float4(oacc[i][j*4+0], oacc[i][j*4+1],
                                                 oacc[i][j*4+2], oacc[i][j*4+3]);
    }
}

extern "C" void kernel_launch(void* const* d_in, const int* in_sizes, int n_in,
                              void* d_out, int out_size) {
    (void)in_sizes; (void)n_in; (void)out_size;
    const float* Q = (const float*)d_in[0];
    const float* K = (const float*)d_in[1];
    const float* V = (const float*)d_in[2];
    float* O = (float*)d_out;
    cudaFuncSetAttribute(attn_headsoftmax_kernel,
                         cudaFuncAttributeMaxDynamicSharedMemorySize, SMEM_BYTES);
    attn_headsoftmax_kernel<<<NB * (SEQ / S_TILE), THREADS, SMEM_BYTES>>>(Q, K, V, O);
}

// round 8
// speedup vs baseline: 1.0002x; 1.0002x over previous
#include <cuda_runtime.h>
#include <cstdint>

// Fused attention with softmax over the HEAD axis (dim=1 quirk).
// B=2, H=8, S=4096, d=64. fp32 end-to-end SIMT baseline.
//
// Layout notes:
//  Q: [B,H,S,64]   K: [B,H,64,S] (pre-transposed)   V: [B,H,S,64]
//  Output reshape in the reference is a RAW reshape of [B,H,S,d], so we
//  write O in [B,H,S,64] contiguous order directly.
//
// Per CTA: one (b, 32-query block), all 8 heads. 512 threads = 16 warps;
// warp w handles head (w>>1), s-half (w&1). Loop over 32-key tiles:
//   1. stage K[8][64][32] and V[8][32][64] tiles in smem
//   2. E[h][s][t] = (Q*scale) @ K  (register micro-tile 2s x 8t per lane)
//   3. softmax over h in smem (local per (s,t) -- no running state needed)
//   4. O[h][s][:] += A @ V  (register micro-tile 2s x 16dv per lane)

namespace {
constexpr int NB = 2, NH = 8, SEQ = 4096, D = 64;
constexpr int S_TILE = 32, T_TILE = 32;
constexpr int ES_LD  = 34;      // padded score-row stride (8B-aligned, bank-spread)
constexpr int THREADS = 512;
constexpr int SMEM_FLOATS = NH*D*S_TILE      // Qs (k-major, scaled)
                          + NH*D*T_TILE      // Ks
                          + NH*T_TILE*D      // Vs
                          + NH*S_TILE*ES_LD; // Es (scores -> weights in place)
constexpr int SMEM_BYTES = SMEM_FLOATS * 4;  // 231424 B <= 232448 B cap
}

__global__ __launch_bounds__(THREADS, 1)
void attn_headsoftmax_kernel(const float* __restrict__ Q,
                             const float* __restrict__ K,
                             const float* __restrict__ V,
                             float* __restrict__ O)
{
    extern __shared__ float smem[];
    float* Qs = smem;                   // [NH][D][S_TILE]  (k-major, s contiguous)
    float* Ks = Qs + NH*D*S_TILE;       // [NH][D][T_TILE]  (k-major, t contiguous)
    float* Vs = Ks + NH*D*T_TILE;       // [NH][T_TILE][D]
    float* Es = Vs + NH*T_TILE*D;       // [NH][S_TILE][ES_LD]

    const int tid  = threadIdx.x;
    const int wid  = tid >> 5;
    const int lane = tid & 31;
    const int b    = blockIdx.x >> 7;             // 128 s-blocks per batch
    const int s0   = (blockIdx.x & 127) * S_TILE;

    const int h     = wid >> 1;                   // warp's head
    const int sbase = (wid & 1) * 16;             // warp's s-half within tile
    const int sg    = lane >> 2;                  // 8 s-groups
    const int tg    = lane & 3;                   // 4 t/dv-groups
    const int sA    = sbase + sg * 2;             // lane's first of 2 s rows

    const float scale = 0.044194173824159216f;    // 1/sqrt(512)

    // ---- stage Q tile once: scaled + transposed to [h][k][s] ----
    {
        const int r    = tid >> 1;                // 0..255 == h*32 + s
        const int half = tid & 1;                 // which 32-wide k half
        const int qh = r >> 5, qs = r & 31;
        const float* src = Q + (((size_t)(b*NH + qh))*SEQ + (size_t)(s0 + qs))*D + half*32;
        #pragma unroll
        for (int m = 0; m < 8; ++m) {
            float4 v = *(const float4*)(src + m*4);
            const int k0 = half*32 + m*4;
            Qs[(qh*D + k0+0)*S_TILE + qs] = v.x * scale;
            Qs[(qh*D + k0+1)*S_TILE + qs] = v.y * scale;
            Qs[(qh*D + k0+2)*S_TILE + qs] = v.z * scale;
            Qs[(qh*D + k0+3)*S_TILE + qs] = v.w * scale;
        }
    }

    float oacc[2][16];                            // lane's O accumulator: 2s x 16dv
    #pragma unroll
    for (int i = 0; i < 2; ++i)
        #pragma unroll
        for (int j = 0; j < 16; ++j) oacc[i][j] = 0.f;

    const size_t kb = ((size_t)b * NH * D) * SEQ; // base of this batch's K rows

    for (int t0g = 0; t0g < SEQ; t0g += T_TILE) {
        __syncthreads();  // previous tile fully consumed (and Qs visible on iter 0)

        // ---- stage K tile: 512 rows (h*64+k) x 32 t, coalesced float4 ----
        #pragma unroll
        for (int i = 0; i < 8; ++i) {
            const int f   = tid + i*THREADS;      // 0..4095 float4s
            const int row = f >> 3;               // h*64 + k
            const int seg = (f & 7) * 4;
            float4 v = *(const float4*)(K + kb + (size_t)row*SEQ + t0g + seg);
            *(float4*)&Ks[row*T_TILE + seg] = v;
        }
        // ---- stage V tile: 256 rows (h*32+t) x 64 dv ----
        #pragma unroll
        for (int i = 0; i < 8; ++i) {
            const int f   = tid + i*THREADS;
            const int row = f >> 4;               // h*32 + t
            const int col = (f & 15) * 4;
            const int vh = row >> 5, vt = row & 31;
            float4 v = *(const float4*)(V + (((size_t)(b*NH + vh))*SEQ + (size_t)(t0g + vt))*D + col);
            *(float4*)&Vs[row*D + col] = v;
        }
        __syncthreads();

        // ---- E[h][s][t] = (Q*scale) @ K : per-lane 2s x 8t micro-tile ----
        {
            float e0[8], e1[8];
            #pragma unroll
            for (int j = 0; j < 8; ++j) { e0[j] = 0.f; e1[j] = 0.f; }
            const float* qb  = Qs + h*D*S_TILE + sA;
            const float* kbp = Ks + h*D*T_TILE + tg*8;
            #pragma unroll 8
            for (int k = 0; k < D; ++k) {
                float2 q  = *(const float2*)(qb  + k*S_TILE);
                float4 b0 = *(const float4*)(kbp + k*T_TILE);
                float4 b1 = *(const float4*)(kbp + k*T_TILE + 4);
                e0[0] += q.x*b0.x; e0[1] += q.x*b0.y; e0[2] += q.x*b0.z; e0[3] += q.x*b0.w;
                e0[4] += q.x*b1.x; e0[5] += q.x*b1.y; e0[6] += q.x*b1.z; e0[7] += q.x*b1.w;
                e1[0] += q.y*b0.x; e1[1] += q.y*b0.y; e1[2] += q.y*b0.z; e1[3] += q.y*b0.w;
                e1[4] += q.y*b1.x; e1[5] += q.y*b1.y; e1[6] += q.y*b1.z; e1[7] += q.y*b1.w;
            }
            float* eb = Es + (h*S_TILE + sA)*ES_LD + tg*8;
            *(float2*)(eb+0) = make_float2(e0[0], e0[1]);
            *(float2*)(eb+2) = make_float2(e0[2], e0[3]);
            *(float2*)(eb+4) = make_float2(e0[4], e0[5]);
            *(float2*)(eb+6) = make_float2(e0[6], e0[7]);
            float* eb1 = eb + ES_LD;
            *(float2*)(eb1+0) = make_float2(e1[0], e1[1]);
            *(float2*)(eb1+2) = make_float2(e1[2], e1[3]);
            *(float2*)(eb1+4) = make_float2(e1[4], e1[5]);
            *(float2*)(eb1+6) = make_float2(e1[6], e1[7]);
        }
        __syncthreads();

        // ---- softmax over the 8 heads, in place (local per (s,t)) ----
        {
            const int ss = tid >> 4;              // s in 0..31
            const int tt = (tid & 15) * 2;        // pair of t positions
            float2 ev[8];
            #pragma unroll
            for (int hh = 0; hh < 8; ++hh)
                ev[hh] = *(const float2*)&Es[(hh*S_TILE + ss)*ES_LD + tt];
            float m0 = ev[0].x, m1 = ev[0].y;
            #pragma unroll
            for (int hh = 1; hh < 8; ++hh) { m0 = fmaxf(m0, ev[hh].x); m1 = fmaxf(m1, ev[hh].y); }
            float sum0 = 0.f, sum1 = 0.f;
            #pragma unroll
            for (int hh = 0; hh < 8; ++hh) {
                ev[hh].x = __expf(ev[hh].x - m0);
                ev[hh].y = __expf(ev[hh].y - m1);
                sum0 += ev[hh].x; sum1 += ev[hh].y;
            }
            const float r0 = __fdividef(1.f, sum0);
            const float r1 = __fdividef(1.f, sum1);
            #pragma unroll
            for (int hh = 0; hh < 8; ++hh)
                *(float2*)&Es[(hh*S_TILE + ss)*ES_LD + tt] =
                    make_float2(ev[hh].x * r0, ev[hh].y * r1);
        }
        __syncthreads();

        // ---- O += A @ V : per-lane 2s x 16dv micro-tile (dv = tg*4 + 16j + r) ----
        {
            const float* ab0 = Es + (h*S_TILE + sA)*ES_LD;
            const float* ab1 = ab0 + ES_LD;
            const float* vb  = Vs + h*T_TILE*D + tg*4;
            #pragma unroll 4
            for (int t = 0; t < T_TILE; ++t) {
                const float a0 = ab0[t];
                const float a1 = ab1[t];
                const float* vr = vb + t*D;
                #pragma unroll
                for (int j = 0; j < 4; ++j) {
                    float4 v = *(const float4*)(vr + j*16);
                    oacc[0][j*4+0] += a0*v.x; oacc[0][j*4+1] += a0*v.y;
                    oacc[0][j*4+2] += a0*v.z; oacc[0][j*4+3] += a0*v.w;
                    oacc[1][j*4+0] += a1*v.x; oacc[1][j*4+1] += a1*v.y;
                    oacc[1][j*4+2] += a1*v.z; oacc[1][j*4+3] += a1*v.w;
                }
            }
        }
    }

    // ---- writeback: raw [B,H,S,64] order == reference's .reshape view ----
    #pragma unroll
    for (int i = 0; i < 2; ++i) {
        float* dst = O + (((size_t)(b*NH + h))*SEQ + (size_t)(s0 + sA + i))*D + tg*4;
        #pragma unroll
        for (int j = 0; j < 4; ++j)
            *(float4*)(dst + j*16) = make_float4(oacc[i][j*4+0], oacc[i][j*4+1],
                                                 oacc[i][j*4+2], oacc[i][j*4+3]);
    }
}

extern "C" void kernel_launch(void* const* d_in, const int* in_sizes, int n_in,
                              void* d_out, int out_size) {
    (void)in_sizes; (void)n_in; (void)out_size;
    const float* Q = (const float*)d_in[0];
    const float* K = (const float*)d_in[1];
    const float* V = (const float*)d_in[2];
    float* O = (float*)d_out;
    cudaFuncSetAttribute(attn_headsoftmax_kernel,
                         cudaFuncAttributeMaxDynamicSharedMemorySize, SMEM_BYTES);
    attn_headsoftmax_kernel<<<NB * (SEQ / S_TILE), THREADS, SMEM_BYTES>>>(Q, K, V, O);
}

// round 9
// speedup vs baseline: 1.0003x; 1.0000x over previous
#include <cuda_runtime.h>
#include <cstdint>

// Fused attention with softmax over the HEAD axis (dim=1 quirk).
// B=2, H=8, S=4096, d=64. fp32 end-to-end SIMT baseline.
//
// Layout notes:
//  Q: [B,H,S,64]   K: [B,H,64,S] (pre-transposed)   V: [B,H,S,64]
//  Output reshape in the reference is a RAW reshape of [B,H,S,d], so we
//  write O in [B,H,S,64] contiguous order directly.
//
// Per CTA: one (b, 32-query block), all 8 heads. 512 threads = 16 warps;
// warp w handles head (w>>1), s-half (w&1). Loop over 32-key tiles:
//   1. stage K[8][64][32] and V[8][32][64] tiles in smem
//   2. E[h][s][t] = (Q*scale) @ K  (register micro-tile 2s x 8t per lane)
//   3. softmax over h in smem (local per (s,t) -- no running state needed)
//   4. O[h][s][:] += A @ V  (register micro-tile 2s x 16dv per lane)

namespace {
constexpr int NB = 2, NH = 8, SEQ = 4096, D = 64;
constexpr int S_TILE = 32, T_TILE = 32;
constexpr int ES_LD  = 34;      // padded score-row stride (8B-aligned, bank-spread)
constexpr int THREADS = 512;
constexpr int SMEM_FLOATS = NH*D*S_TILE      // Qs (k-major, scaled)
                          + NH*D*T_TILE      // Ks
                          + NH*T_TILE*D      // Vs
                          + NH*S_TILE*ES_LD; // Es (scores -> weights in place)
constexpr int SMEM_BYTES = SMEM_FLOATS * 4;  // 231424 B <= 232448 B cap
}

__global__ __launch_bounds__(THREADS, 1)
void attn_headsoftmax_kernel(const float* __restrict__ Q,
                             const float* __restrict__ K,
                             const float* __restrict__ V,
                             float* __restrict__ O)
{
    extern __shared__ float smem[];
    float* Qs = smem;                   // [NH][D][S_TILE]  (k-major, s contiguous)
    float* Ks = Qs + NH*D*S_TILE;       // [NH][D][T_TILE]  (k-major, t contiguous)
    float* Vs = Ks + NH*D*T_TILE;       // [NH][T_TILE][D]
    float* Es = Vs + NH*T_TILE*D;       // [NH][S_TILE][ES_LD]

    const int tid  = threadIdx.x;
    const int wid  = tid >> 5;
    const int lane = tid & 31;
    const int b    = blockIdx.x >> 7;             // 128 s-blocks per batch
    const int s0   = (blockIdx.x & 127) * S_TILE;

    const int h     = wid >> 1;                   // warp's head
    const int sbase = (wid & 1) * 16;             // warp's s-half within tile
    const int sg    = lane >> 2;                  // 8 s-groups
    const int tg    = lane & 3;                   // 4 t/dv-groups
    const int sA    = sbase + sg * 2;             // lane's first of 2 s rows

    const float scale = 0.044194173824159216f;    // 1/sqrt(512)

    // ---- stage Q tile once: scaled + transposed to [h][k][s] ----
    {
        const int r    = tid >> 1;                // 0..255 == h*32 + s
        const int half = tid & 1;                 // which 32-wide k half
        const int qh = r >> 5, qs = r & 31;
        const float* src = Q + (((size_t)(b*NH + qh))*SEQ + (size_t)(s0 + qs))*D + half*32;
        #pragma unroll
        for (int m = 0; m < 8; ++m) {
            float4 v = *(const float4*)(src + m*4);
            const int k0 = half*32 + m*4;
            Qs[(qh*D + k0+0)*S_TILE + qs] = v.x * scale;
            Qs[(qh*D + k0+1)*S_TILE + qs] = v.y * scale;
            Qs[(qh*D + k0+2)*S_TILE + qs] = v.z * scale;
            Qs[(qh*D + k0+3)*S_TILE + qs] = v.w * scale;
        }
    }

    float oacc[2][16];                            // lane's O accumulator: 2s x 16dv
    #pragma unroll
    for (int i = 0; i < 2; ++i)
        #pragma unroll
        for (int j = 0; j < 16; ++j) oacc[i][j] = 0.f;

    const size_t kb = ((size_t)b * NH * D) * SEQ; // base of this batch's K rows

    for (int t0g = 0; t0g < SEQ; t0g += T_TILE) {
        __syncthreads();  // previous tile fully consumed (and Qs visible on iter 0)

        // ---- stage K tile: 512 rows (h*64+k) x 32 t, coalesced float4 ----
        #pragma unroll
        for (int i = 0; i < 8; ++i) {
            const int f   = tid + i*THREADS;      // 0..4095 float4s
            const int row = f >> 3;               // h*64 + k
            const int seg = (f & 7) * 4;
            float4 v = *(const float4*)(K + kb + (size_t)row*SEQ + t0g + seg);
            *(float4*)&Ks[row*T_TILE + seg] = v;
        }
        // ---- stage V tile: 256 rows (h*32+t) x 64 dv ----
        #pragma unroll
        for (int i = 0; i < 8; ++i) {
            const int f   = tid + i*THREADS;
            const int row = f >> 4;               // h*32 + t
            const int col = (f & 15) * 4;
            const int vh = row >> 5, vt = row & 31;
            float4 v = *(const float4*)(V + (((size_t)(b*NH + vh))*SEQ + (size_t)(t0g + vt))*D + col);
            *(float4*)&Vs[row*D + col] = v;
        }
        __syncthreads();

        // ---- E[h][s][t] = (Q*scale) @ K : per-lane 2s x 8t micro-tile ----
        {
            float e0[8], e1[8];
            #pragma unroll
            for (int j = 0; j < 8; ++j) { e0[j] = 0.f; e1[j] = 0.f; }
            const float* qb  = Qs + h*D*S_TILE + sA;
            const float* kbp = Ks + h*D*T_TILE + tg*8;
            #pragma unroll 8
            for (int k = 0; k < D; ++k) {
                float2 q  = *(const float2*)(qb  + k*S_TILE);
                float4 b0 = *(const float4*)(kbp + k*T_TILE);
                float4 b1 = *(const float4*)(kbp + k*T_TILE + 4);
                e0[0] += q.x*b0.x; e0[1] += q.x*b0.y; e0[2] += q.x*b0.z; e0[3] += q.x*b0.w;
                e0[4] += q.x*b1.x; e0[5] += q.x*b1.y; e0[6] += q.x*b1.z; e0[7] += q.x*b1.w;
                e1[0] += q.y*b0.x; e1[1] += q.y*b0.y; e1[2] += q.y*b0.z; e1[3] += q.y*b0.w;
                e1[4] += q.y*b1.x; e1[5] += q.y*b1.y; e1[6] += q.y*b1.z; e1[7] += q.y*b1.w;
            }
            float* eb = Es + (h*S_TILE + sA)*ES_LD + tg*8;
            *(float2*)(eb+0) = make_float2(e0[0], e0[1]);
            *(float2*)(eb+2) = make_float2(e0[2], e0[3]);
            *(float2*)(eb+4) = make_float2(e0[4], e0[5]);
            *(float2*)(eb+6) = make_float2(e0[6], e0[7]);
            float* eb1 = eb + ES_LD;
            *(float2*)(eb1+0) = make_float2(e1[0], e1[1]);
            *(float2*)(eb1+2) = make_float2(e1[2], e1[3]);
            *(float2*)(eb1+4) = make_float2(e1[4], e1[5]);
            *(float2*)(eb1+6) = make_float2(e1[6], e1[7]);
        }
        __syncthreads();

        // ---- softmax over the 8 heads, in place (local per (s,t)) ----
        {
            const int ss = tid >> 4;              // s in 0..31
            const int tt = (tid & 15) * 2;        // pair of t positions
            float2 ev[8];
            #pragma unroll
            for (int hh = 0; hh < 8; ++hh)
                ev[hh] = *(const float2*)&Es[(hh*S_TILE + ss)*ES_LD + tt];
            float m0 = ev[0].x, m1 = ev[0].y;
            #pragma unroll
            for (int hh = 1; hh < 8; ++hh) { m0 = fmaxf(m0, ev[hh].x); m1 = fmaxf(m1, ev[hh].y); }
            float sum0 = 0.f, sum1 = 0.f;
            #pragma unroll
            for (int hh = 0; hh < 8; ++hh) {
                ev[hh].x = __expf(ev[hh].x - m0);
                ev[hh].y = __expf(ev[hh].y - m1);
                sum0 += ev[hh].x; sum1 += ev[hh].y;
            }
            const float r0 = __fdividef(1.f, sum0);
            const float r1 = __fdividef(1.f, sum1);
            #pragma unroll
            for (int hh = 0; hh < 8; ++hh)
                *(float2*)&Es[(hh*S_TILE + ss)*ES_LD + tt] =
                    make_float2(ev[hh].x * r0, ev[hh].y * r1);
        }
        __syncthreads();

        // ---- O += A @ V : per-lane 2s x 16dv micro-tile (dv = tg*4 + 16j + r) ----
        {
            const float* ab0 = Es + (h*S_TILE + sA)*ES_LD;
            const float* ab1 = ab0 + ES_LD;
            const float* vb  = Vs + h*T_TILE*D + tg*4;
            #pragma unroll 4
            for (int t = 0; t < T_TILE; ++t) {
                const float a0 = ab0[t];
                const float a1 = ab1[t];
                const float* vr = vb + t*D;
                #pragma unroll
                for (int j = 0; j < 4; ++j) {
                    float4 v = *(const float4*)(vr + j*16);
                    oacc[0][j*4+0] += a0*v.x; oacc[0][j*4+1] += a0*v.y;
                    oacc[0][j*4+2] += a0*v.z; oacc[0][j*4+3] += a0*v.w;
                    oacc[1][j*4+0] += a1*v.x; oacc[1][j*4+1] += a1*v.y;
                    oacc[1][j*4+2] += a1*v.z; oacc[1][j*4+3] += a1*v.w;
                }
            }
        }
    }

    // ---- writeback: raw [B,H,S,64] order == reference's .reshape view ----
    #pragma unroll
    for (int i = 0; i < 2; ++i) {
        float* dst = O + (((size_t)(b*NH + h))*SEQ + (size_t)(s0 + sA + i))*D + tg*4;
        #pragma unroll
        for (int j = 0; j < 4; ++j)
            *(float4*)(dst + j*16) = make_float4(oacc[i][j*4+0], oacc[i][j*4+1],
                                                 oacc[i][j*4+2], oacc[i][j*4+3]);
    }
}

extern "C" void kernel_launch(void* const* d_in, const int* in_sizes, int n_in,
                              void* d_out, int out_size) {
    (void)in_sizes; (void)n_in; (void)out_size;
    const float* Q = (const float*)d_in[0];
    const float* K = (const float*)d_in[1];
    const float* V = (const float*)d_in[2];
    float* O = (float*)d_out;
    cudaFuncSetAttribute(attn_headsoftmax_kernel,
                         cudaFuncAttributeMaxDynamicSharedMemorySize, SMEM_BYTES);
    attn_headsoftmax_kernel<<<NB * (SEQ / S_TILE), THREADS, SMEM_BYTES>>>(Q, K, V, O);
}

// round 11
// speedup vs baseline: 3.7398x; 3.7388x over previous
#include <cuda_runtime.h>
#include <cuda_fp16.h>
#include <cstdint>

// Head-axis-softmax attention, HMMA (mma.sync) fp16 operands / f32 accum.
// B=2,H=8,S=4096,d=64. Grid 256 = b x 128 s-blocks of 32. 512 threads = 16 warps;
// warp = (head h = w>>1, s-half = w&1). Per 32-key tile:
//   stage K/V -> f16 smem; GEMM1 E = Qh @ K (mma.sync); E -> f16 smem exchange;
//   softmax over 8 heads in f32; W -> f16 smem; GEMM2 O += W @ V (mma.sync).
// Output written in raw [B,H,S,64] order (== reference reshape).

namespace {
constexpr int NH = 8, SEQ = 4096, D = 64;
constexpr int S_TILE = 32, T_TILE = 32;
constexpr int THREADS = 512;
constexpr float SCALE = 0.044194173824159216f;   // 1/sqrt(512)

// smem byte layout (rows padded for bank-conflict-free ldmatrix/LDS)
constexpr int KS_ROW = 80;    // 32 t * 2B = 64B data, pad 80  (16B-aligned, 5r mod 8 distinct)
constexpr int VS_ROW = 144;   // 64 dv * 2B = 128B data, pad 144 (9r mod 8 distinct)
constexpr int ES_ROW = 72;    // 32 t * 2B = 64B data, pad 72
constexpr int WS_ROW = 80;    // 32 t * 2B = 64B data, pad 80
constexpr int QS_ROW = 144;   // 64 k * 2B = 128B data, pad 144 (staging only)

constexpr int SM_K = 0;                         // Ks: 8h * 64k rows * 80  = 40960
constexpr int SM_V = 40960;                     // Vs: 8h * 32t rows * 144 = 36864
constexpr int SM_E = SM_V + 36864;              // Es: 256 rows * 72       = 18432
constexpr int SM_W = SM_E + 18432;              // Ws: 8h * 32s rows * 80  = 20480
constexpr int SMEM_BYTES = SM_W + 20480;        // 116736
constexpr int SM_Q = 0;                         // Q staging aliases Ks (36864 <= 40960)
constexpr int KS_H = 64 * KS_ROW;               // 5120 per head
constexpr int VS_H = 32 * VS_ROW;               // 4608
constexpr int WS_H = 32 * WS_ROW;               // 2560
constexpr int QS_H = 32 * QS_ROW;               // 4608
}

static __device__ __forceinline__ uint32_t smem_u32(const void* p) {
    uint32_t a;
    asm("{ .reg .u64 t; cvta.to.shared.u64 t, %1; cvt.u32.u64 %0, t; }" : "=r"(a) : "l"(p));
    return a;
}
static __device__ __forceinline__ void ldsm_x4(uint32_t* r, uint32_t a) {
    asm volatile("ldmatrix.sync.aligned.m8n8.x4.shared.b16 {%0,%1,%2,%3}, [%4];"
        : "=r"(r[0]), "=r"(r[1]), "=r"(r[2]), "=r"(r[3]) : "r"(a));
}
static __device__ __forceinline__ void ldsm_x2t(uint32_t* r, uint32_t a) {
    asm volatile("ldmatrix.sync.aligned.m8n8.x2.trans.shared.b16 {%0,%1}, [%2];"
        : "=r"(r[0]), "=r"(r[1]) : "r"(a));
}
static __device__ __forceinline__ void mma16816(float* c, const uint32_t* a, const uint32_t* b) {
    asm volatile("mma.sync.aligned.m16n8k16.row.col.f32.f16.f16.f32 "
        "{%0,%1,%2,%3}, {%4,%5,%6,%7}, {%8,%9}, {%0,%1,%2,%3};"
        : "+f"(c[0]), "+f"(c[1]), "+f"(c[2]), "+f"(c[3])
        : "r"(a[0]), "r"(a[1]), "r"(a[2]), "r"(a[3]), "r"(b[0]), "r"(b[1]));
}
static __device__ __forceinline__ uint32_t packh2(float x, float y) {
    __half2 h = __floats2half2_rn(x, y);
    return *(const uint32_t*)&h;
}

__global__ __launch_bounds__(THREADS, 1)
void attn_hmma_kernel(const float* __restrict__ Q, const float* __restrict__ K,
                      const float* __restrict__ V, float* __restrict__ O)
{
    extern __shared__ char smem[];
    const uint32_t sb = smem_u32(smem);
    const int tid  = threadIdx.x;
    const int wid  = tid >> 5, lane = tid & 31;
    const int b    = blockIdx.x >> 7;
    const int s0   = (blockIdx.x & 127) * S_TILE;
    const int h    = wid >> 1;            // warp's head
    const int half = wid & 1;             // warp's 16-row s-half

    // ---- stage Q (scaled, fp16) into SM_Q, then load persistent A-fragments ----
    #pragma unroll
    for (int i = 0; i < 4; ++i) {
        const int f = tid + i * THREADS;            // 0..2047
        const int qh = f >> 8, rem = f & 255;
        const int s = rem >> 3, kseg = (rem & 7) * 8;
        const float* src = Q + (((size_t)(b * NH + qh)) * SEQ + (s0 + s)) * D + kseg;
        float4 v0 = *(const float4*)src;
        float4 v1 = *(const float4*)(src + 4);
        uint32_t p[4] = { packh2(v0.x * SCALE, v0.y * SCALE), packh2(v0.z * SCALE, v0.w * SCALE),
                          packh2(v1.x * SCALE, v1.y * SCALE), packh2(v1.z * SCALE, v1.w * SCALE) };
        *(uint4*)(smem + SM_Q + qh * QS_H + s * QS_ROW + kseg * 2) = *(const uint4*)p;
    }
    __syncthreads();

    uint32_t qa[4][4];    // persistent Q A-fragments, 4 k-steps of 16
    {
        const uint32_t base = sb + SM_Q + h * QS_H + (half * 16 + (lane & 15)) * QS_ROW
                            + (lane >> 4) * 16;
        #pragma unroll
        for (int k0 = 0; k0 < 4; ++k0) ldsm_x4(qa[k0], base + k0 * 32);
    }

    float o[8][4];        // O accumulator: 16s x 64dv per warp (8 n-steps)
    #pragma unroll
    for (int n = 0; n < 8; ++n)
        #pragma unroll
        for (int i = 0; i < 4; ++i) o[n][i] = 0.f;

    const size_t kbase = (size_t)b * NH * D * SEQ;

    for (int t0g = 0; t0g < SEQ; t0g += T_TILE) {
        __syncthreads();   // Q-frags loaded (iter 0) / prev tile's Ws,Vs consumed

        // ---- stage K tile: Ks[h][k][t] f16, read along t (coalesced 128B) ----
        #pragma unroll
        for (int i = 0; i < 4; ++i) {
            const int f = tid + i * THREADS;        // 0..2047
            const int kh = f >> 8, rem = f & 255;
            const int k = rem >> 2, tseg = (rem & 3) * 8;
            const float* src = K + kbase + (size_t)(kh * D + k) * SEQ + t0g + tseg;
            float4 v0 = *(const float4*)src;
            float4 v1 = *(const float4*)(src + 4);
            uint32_t p[4] = { packh2(v0.x, v0.y), packh2(v0.z, v0.w),
                              packh2(v1.x, v1.y), packh2(v1.z, v1.w) };
            *(uint4*)(smem + SM_K + kh * KS_H + k * KS_ROW + tseg * 2) = *(const uint4*)p;
        }
        // ---- stage V tile: Vs[h][t][dv] f16, read along dv (coalesced 256B) ----
        #pragma unroll
        for (int i = 0; i < 4; ++i) {
            const int f = tid + i * THREADS;
            const int vh = f >> 8, rem = f & 255;
            const int t = rem >> 3, dseg = (rem & 7) * 8;
            const float* src = V + (((size_t)(b * NH + vh)) * SEQ + (t0g + t)) * D + dseg;
            float4 v0 = *(const float4*)src;
            float4 v1 = *(const float4*)(src + 4);
            uint32_t p[4] = { packh2(v0.x, v0.y), packh2(v0.z, v0.w),
                              packh2(v1.x, v1.y), packh2(v1.z, v1.w) };
            *(uint4*)(smem + SM_V + vh * VS_H + t * VS_ROW + dseg * 2) = *(const uint4*)p;
        }
        __syncthreads();

        // ---- GEMM1: E[16s x 32t] = Qh @ K  (4 k-steps x 4 n-steps) ----
        float c1[4][4];
        #pragma unroll
        for (int n = 0; n < 4; ++n)
            #pragma unroll
            for (int i = 0; i < 4; ++i) c1[n][i] = 0.f;
        {
            const uint32_t kb = sb + SM_K + h * KS_H + (lane & 15) * KS_ROW;
            #pragma unroll
            for (int k0 = 0; k0 < 4; ++k0) {
                #pragma unroll
                for (int n0 = 0; n0 < 4; ++n0) {
                    uint32_t bf[2];
                    ldsm_x2t(bf, kb + k0 * 16 * KS_ROW + n0 * 16);
                    mma16816(c1[n0], qa[k0], bf);
                }
            }
        }
        // ---- E -> f16 smem exchange ----
        {
            const int r0 = h * S_TILE + half * 16 + (lane >> 2);
            const int cb = (lane & 3) * 4;
            #pragma unroll
            for (int n0 = 0; n0 < 4; ++n0) {
                *(uint32_t*)(smem + SM_E + r0 * ES_ROW + n0 * 16 + cb) =
                    packh2(c1[n0][0], c1[n0][1]);
                *(uint32_t*)(smem + SM_E + (r0 + 8) * ES_ROW + n0 * 16 + cb) =
                    packh2(c1[n0][2], c1[n0][3]);
            }
        }
        __syncthreads();

        // ---- softmax over 8 heads: thread = (s = tid>>4, t-pair = tid&15) ----
        {
            const int s = tid >> 4, tp = tid & 15;
            float ex[16];
            float sum0 = 0.f, sum1 = 0.f;
            #pragma unroll
            for (int hh = 0; hh < 8; ++hh) {
                __half2 hv = *(const __half2*)(smem + SM_E + (hh * S_TILE + s) * ES_ROW + tp * 4);
                float2 f = __half22float2(hv);
                ex[2 * hh]     = __expf(f.x);
                ex[2 * hh + 1] = __expf(f.y);
                sum0 += ex[2 * hh];
                sum1 += ex[2 * hh + 1];
            }
            const float r0 = __fdividef(1.f, sum0);
            const float r1 = __fdividef(1.f, sum1);
            #pragma unroll
            for (int hh = 0; hh < 8; ++hh)
                *(uint32_t*)(smem + SM_W + hh * WS_H + s * WS_ROW + tp * 4) =
                    packh2(ex[2 * hh] * r0, ex[2 * hh + 1] * r1);
        }
        __syncthreads();

        // ---- GEMM2: O += W[16s x 32t] @ V[32t x 64dv] (2 k-steps x 8 n-steps) ----
        {
            uint32_t a2[2][4];
            const uint32_t wb = sb + SM_W + h * WS_H + (half * 16 + (lane & 15)) * WS_ROW
                              + (lane >> 4) * 16;
            #pragma unroll
            for (int k0 = 0; k0 < 2; ++k0) ldsm_x4(a2[k0], wb + k0 * 32);
            const uint32_t vb = sb + SM_V + h * VS_H + (lane & 15) * VS_ROW;
            #pragma unroll
            for (int n0 = 0; n0 < 8; ++n0) {
                #pragma unroll
                for (int k0 = 0; k0 < 2; ++k0) {
                    uint32_t bf[2];
                    ldsm_x2t(bf, vb + k0 * 16 * VS_ROW + n0 * 16);
                    mma16816(o[n0], a2[k0], bf);
                }
            }
        }
    }

    // ---- writeback: lane holds rows r, r+8; cols 2(lane&3)+n0*8 ----
    {
        const int r = half * 16 + (lane >> 2);
        const int c = (lane & 3) * 2;
        float* dst = O + (((size_t)(b * NH + h)) * SEQ + (s0 + r)) * D;
        #pragma unroll
        for (int n0 = 0; n0 < 8; ++n0) {
            *(float2*)(dst + n0 * 8 + c)           = make_float2(o[n0][0], o[n0][1]);
            *(float2*)(dst + 8 * D + n0 * 8 + c)   = make_float2(o[n0][2], o[n0][3]);
        }
    }
}

extern "C" void kernel_launch(void* const* d_in, const int* in_sizes, int n_in,
                              void* d_out, int out_size) {
    (void)in_sizes; (void)n_in; (void)out_size;
    const float* Q = (const float*)d_in[0];
    const float* K = (const float*)d_in[1];
    const float* V = (const float*)d_in[2];
    float* O = (float*)d_out;
    cudaFuncSetAttribute(attn_hmma_kernel,
                         cudaFuncAttributeMaxDynamicSharedMemorySize, SMEM_BYTES);
    attn_hmma_kernel<<<2 * (SEQ / S_TILE), THREADS, SMEM_BYTES>>>(Q, K, V, O);
}

// round 12
// speedup vs baseline: 4.8368x; 1.2933x over previous
#include <cuda_runtime.h>
#include <cuda_fp16.h>
#include <cstdint>

// Head-axis-softmax attention, HMMA fp16/f32, with:
//  - one-time K/V f32->f16 pre-pass into __device__ scratch
//  - cp.async.cg staging of f16 tiles (no register round-trip)
//  - double-buffered K/V with one-tile prefetch lookahead
//  - merged E/W exchange buffer (in-place softmax, thread-exclusive addresses)
// B=2,H=8,S=4096,d=64. Grid 256 = b x 128 s-blocks of 32. 512 threads = 16 warps;
// warp = (head h = w>>1, s-half = w&1).

namespace {
constexpr int NH = 8, SEQ = 4096, D = 64;
constexpr int S_TILE = 32, T_TILE = 32;
constexpr int THREADS = 512;
constexpr float SCALE = 0.044194173824159216f;   // 1/sqrt(512)

constexpr int KS_ROW = 80;    // [k:64][t:32 f16=64B] rows, pad 80 (16B-mult, conflict-free)
constexpr int VS_ROW = 144;   // [t:32][dv:64 f16=128B] rows, pad 144
constexpr int EW_ROW = 80;    // merged E/W: [h][s:32][t:32 f16=64B] rows, pad 80
constexpr int QS_ROW = 144;   // Q staging rows (64 k f16 = 128B, pad 144)

constexpr int KS_H = 64 * KS_ROW;               // 5120 per head
constexpr int VS_H = 32 * VS_ROW;               // 4608 per head
constexpr int EW_H = 32 * EW_ROW;               // 2560 per head
constexpr int QS_H = 32 * QS_ROW;               // 4608 per head

constexpr int BUF_STRIDE = NH * KS_H + NH * VS_H;   // 40960 + 36864 = 77824
constexpr int SM_EW = 2 * BUF_STRIDE;               // 155648
constexpr int SMEM_BYTES = SM_EW + NH * EW_H;       // 176128
constexpr int SM_Q = BUF_STRIDE;                    // Q staging aliases buf1 K region

constexpr int KV_ELEMS = 2 * NH * D * SEQ;          // 4194304 per tensor
}

static __device__ __align__(16) __half g_K16[KV_ELEMS];
static __device__ __align__(16) __half g_V16[KV_ELEMS];

// ---- pre-pass: f32 -> f16 for K and V ----
__global__ __launch_bounds__(256) void cvt_kv_kernel(const float* __restrict__ K,
                                                     const float* __restrict__ V) {
    const int i = (blockIdx.x * 256 + threadIdx.x) * 8;
    {
        float4 a = *(const float4*)(K + i);
        float4 b = *(const float4*)(K + i + 4);
        __half2 p[4] = { __floats2half2_rn(a.x, a.y), __floats2half2_rn(a.z, a.w),
                         __floats2half2_rn(b.x, b.y), __floats2half2_rn(b.z, b.w) };
        *(uint4*)&g_K16[i] = *(const uint4*)p;
    }
    {
        float4 a = *(const float4*)(V + i);
        float4 b = *(const float4*)(V + i + 4);
        __half2 p[4] = { __floats2half2_rn(a.x, a.y), __floats2half2_rn(a.z, a.w),
                         __floats2half2_rn(b.x, b.y), __floats2half2_rn(b.z, b.w) };
        *(uint4*)&g_V16[i] = *(const uint4*)p;
    }
}

static __device__ __forceinline__ uint32_t smem_u32(const void* p) {
    uint32_t a;
    asm("{ .reg .u64 t; cvta.to.shared.u64 t, %1; cvt.u32.u64 %0, t; }" : "=r"(a) : "l"(p));
    return a;
}
static __device__ __forceinline__ void cp16(uint32_t dst, const void* src) {
    asm volatile("cp.async.cg.shared.global [%0], [%1], 16;" :: "r"(dst), "l"(src));
}
static __device__ __forceinline__ void cp_commit() {
    asm volatile("cp.async.commit_group;" ::: "memory");
}
static __device__ __forceinline__ void cp_wait1() {
    asm volatile("cp.async.wait_group 1;" ::: "memory");
}
static __device__ __forceinline__ void ldsm_x4(uint32_t* r, uint32_t a) {
    asm volatile("ldmatrix.sync.aligned.m8n8.x4.shared.b16 {%0,%1,%2,%3}, [%4];"
        : "=r"(r[0]), "=r"(r[1]), "=r"(r[2]), "=r"(r[3]) : "r"(a));
}
static __device__ __forceinline__ void ldsm_x2t(uint32_t* r, uint32_t a) {
    asm volatile("ldmatrix.sync.aligned.m8n8.x2.trans.shared.b16 {%0,%1}, [%2];"
        : "=r"(r[0]), "=r"(r[1]) : "r"(a));
}
static __device__ __forceinline__ void mma16816(float* c, const uint32_t* a, const uint32_t* b) {
    asm volatile("mma.sync.aligned.m16n8k16.row.col.f32.f16.f16.f32 "
        "{%0,%1,%2,%3}, {%4,%5,%6,%7}, {%8,%9}, {%0,%1,%2,%3};"
        : "+f"(c[0]), "+f"(c[1]), "+f"(c[2]), "+f"(c[3])
        : "r"(a[0]), "r"(a[1]), "r"(a[2]), "r"(a[3]), "r"(b[0]), "r"(b[1]));
}
static __device__ __forceinline__ uint32_t packh2(float x, float y) {
    __half2 h = __floats2half2_rn(x, y);
    return *(const uint32_t*)&h;
}

__global__ __launch_bounds__(THREADS, 1)
void attn_hmma_kernel(const float* __restrict__ Q, float* __restrict__ O)
{
    extern __shared__ char smem[];
    const uint32_t sb = smem_u32(smem);
    const int tid  = threadIdx.x;
    const int wid  = tid >> 5, lane = tid & 31;
    const int b    = blockIdx.x >> 7;
    const int s0   = (blockIdx.x & 127) * S_TILE;
    const int h    = wid >> 1;            // warp's head
    const int half = wid & 1;             // warp's 16-row s-half

    const size_t kv16 = (size_t)b * NH * D * SEQ;  // element base into g_K16/g_V16

    // ---- prefetch lambda: stage one 32-key tile (f16) into buffer `buf` ----
    auto prefetch = [&](int t0, int buf) {
        const uint32_t kdst = sb + buf * BUF_STRIDE;
        const uint32_t vdst = kdst + NH * KS_H;
        #pragma unroll
        for (int i = 0; i < 4; ++i) {
            const int f = tid + i * THREADS;           // 0..2047
            const int kh = f >> 8, rem = f & 255;
            const int k = rem >> 2, ts = (rem & 3) * 8;
            cp16(kdst + kh * KS_H + k * KS_ROW + ts * 2,
                 g_K16 + kv16 + (size_t)(kh * D + k) * SEQ + t0 + ts);
        }
        #pragma unroll
        for (int i = 0; i < 4; ++i) {
            const int f = tid + i * THREADS;
            const int vh = f >> 8, rem = f & 255;
            const int t = rem >> 3, ds = (rem & 7) * 8;
            cp16(vdst + vh * VS_H + t * VS_ROW + ds * 2,
                 g_V16 + kv16 + ((size_t)vh * SEQ + t0 + t) * D + ds);
        }
    };

    // ---- stage Q (scaled, f16) into buf1's K region, load persistent A-frags ----
    #pragma unroll
    for (int i = 0; i < 4; ++i) {
        const int f = tid + i * THREADS;               // 0..2047
        const int qh = f >> 8, rem = f & 255;
        const int s = rem >> 3, kseg = (rem & 7) * 8;
        const float* src = Q + (((size_t)(b * NH + qh)) * SEQ + (s0 + s)) * D + kseg;
        float4 v0 = *(const float4*)src;
        float4 v1 = *(const float4*)(src + 4);
        uint32_t p[4] = { packh2(v0.x * SCALE, v0.y * SCALE), packh2(v0.z * SCALE, v0.w * SCALE),
                          packh2(v1.x * SCALE, v1.y * SCALE), packh2(v1.z * SCALE, v1.w * SCALE) };
        *(uint4*)(smem + SM_Q + qh * QS_H + s * QS_ROW + kseg * 2) = *(const uint4*)p;
    }
    prefetch(0, 0);          // tile0 -> buf0 (disjoint from Q region)
    cp_commit();
    __syncthreads();

    uint32_t qa[4][4];       // persistent Q A-fragments, 4 k-steps of 16
    {
        const uint32_t base = sb + SM_Q + h * QS_H + (half * 16 + (lane & 15)) * QS_ROW
                            + (lane >> 4) * 16;
        #pragma unroll
        for (int k0 = 0; k0 < 4; ++k0) ldsm_x4(qa[k0], base + k0 * 32);
    }
    __syncthreads();         // everyone done reading Q region before buf1 prefetch overwrites
    prefetch(T_TILE, 1);     // tile1 -> buf1
    cp_commit();

    float o[8][4];           // O accumulator: 16s x 64dv per warp
    #pragma unroll
    for (int n = 0; n < 8; ++n)
        #pragma unroll
        for (int i = 0; i < 4; ++i) o[n][i] = 0.f;

    for (int t0g = 0; t0g < SEQ; t0g += T_TILE) {
        const int buf = (t0g >> 5) & 1;
        const uint32_t kbase = sb + buf * BUF_STRIDE;
        const uint32_t vbase = kbase + NH * KS_H;

        cp_wait1();          // current tile's group complete (next may still fly)
        __syncthreads();

        // ---- GEMM1: E[16s x 32t] = Qh @ K  (4 k-steps x 4 n-steps) ----
        float c1[4][4];
        #pragma unroll
        for (int n = 0; n < 4; ++n)
            #pragma unroll
            for (int i = 0; i < 4; ++i) c1[n][i] = 0.f;
        {
            const uint32_t kb = kbase + h * KS_H + (lane & 15) * KS_ROW;
            #pragma unroll
            for (int k0 = 0; k0 < 4; ++k0) {
                #pragma unroll
                for (int n0 = 0; n0 < 4; ++n0) {
                    uint32_t bf[2];
                    ldsm_x2t(bf, kb + k0 * 16 * KS_ROW + n0 * 16);
                    mma16816(c1[n0], qa[k0], bf);
                }
            }
        }
        // ---- E -> f16 exchange (merged E/W buffer) ----
        {
            const int r0 = half * 16 + (lane >> 2);
            const int cb = (lane & 3) * 4;
            char* ebase = smem + SM_EW + h * EW_H;
            #pragma unroll
            for (int n0 = 0; n0 < 4; ++n0) {
                *(uint32_t*)(ebase + r0 * EW_ROW + n0 * 16 + cb) = packh2(c1[n0][0], c1[n0][1]);
                *(uint32_t*)(ebase + (r0 + 8) * EW_ROW + n0 * 16 + cb) = packh2(c1[n0][2], c1[n0][3]);
            }
        }
        __syncthreads();

        // ---- softmax over 8 heads, in place (thread-exclusive addresses) ----
        {
            const int s = tid >> 4, tp = tid & 15;
            float ex[16];
            float sum0 = 0.f, sum1 = 0.f;
            #pragma unroll
            for (int hh = 0; hh < 8; ++hh) {
                __half2 hv = *(const __half2*)(smem + SM_EW + hh * EW_H + s * EW_ROW + tp * 4);
                float2 f = __half22float2(hv);
                ex[2 * hh]     = __expf(f.x);
                ex[2 * hh + 1] = __expf(f.y);
                sum0 += ex[2 * hh];
                sum1 += ex[2 * hh + 1];
            }
            const float r0 = __fdividef(1.f, sum0);
            const float r1 = __fdividef(1.f, sum1);
            #pragma unroll
            for (int hh = 0; hh < 8; ++hh)
                *(uint32_t*)(smem + SM_EW + hh * EW_H + s * EW_ROW + tp * 4) =
                    packh2(ex[2 * hh] * r0, ex[2 * hh + 1] * r1);
        }
        __syncthreads();

        // ---- GEMM2: O += W[16s x 32t] @ V[32t x 64dv] ----
        {
            uint32_t a2[2][4];
            const uint32_t wb = sb + SM_EW + h * EW_H + (half * 16 + (lane & 15)) * EW_ROW
                              + (lane >> 4) * 16;
            #pragma unroll
            for (int k0 = 0; k0 < 2; ++k0) ldsm_x4(a2[k0], wb + k0 * 32);
            const uint32_t vb = vbase + h * VS_H + (lane & 15) * VS_ROW;
            #pragma unroll
            for (int n0 = 0; n0 < 8; ++n0) {
                #pragma unroll
                for (int k0 = 0; k0 < 2; ++k0) {
                    uint32_t bf[2];
                    ldsm_x2t(bf, vb + k0 * 16 * VS_ROW + n0 * 16);
                    mma16816(o[n0], a2[k0], bf);
                }
            }
        }
        __syncthreads();     // buffer `buf` fully consumed by all warps

        const int tn = t0g + 2 * T_TILE;
        if (tn < SEQ) prefetch(tn, buf);
        cp_commit();         // always commit (keeps group arithmetic uniform)
    }

    // ---- writeback: raw [B,H,S,64] order ----
    {
        const int r = half * 16 + (lane >> 2);
        const int c = (lane & 3) * 2;
        float* dst = O + (((size_t)(b * NH + h)) * SEQ + (s0 + r)) * D;
        #pragma unroll
        for (int n0 = 0; n0 < 8; ++n0) {
            *(float2*)(dst + n0 * 8 + c)         = make_float2(o[n0][0], o[n0][1]);
            *(float2*)(dst + 8 * D + n0 * 8 + c) = make_float2(o[n0][2], o[n0][3]);
        }
    }
}

extern "C" void kernel_launch(void* const* d_in, const int* in_sizes, int n_in,
                              void* d_out, int out_size) {
    (void)in_sizes; (void)n_in; (void)out_size;
    const float* Q = (const float*)d_in[0];
    const float* K = (const float*)d_in[1];
    const float* V = (const float*)d_in[2];
    float* O = (float*)d_out;
    cvt_kv_kernel<<<KV_ELEMS / 8 / 256, 256>>>(K, V);
    cudaFuncSetAttribute(attn_hmma_kernel,
                         cudaFuncAttributeMaxDynamicSharedMemorySize, SMEM_BYTES);
    attn_hmma_kernel<<<2 * (SEQ / S_TILE), THREADS, SMEM_BYTES>>>(Q, O);
}

// round 13
// speedup vs baseline: 6.7445x; 1.3944x over previous
#include <cuda_runtime.h>
#include <cuda_fp16.h>
#include <cstdint>

// Head-axis-softmax attention, HMMA fp16/f32.
// R13: S_TILE=64 (grid 128 = one wave), 2 m-tiles/warp with B-fragment reuse,
// Q staged in smem (re-ldmatrix per tile), phase-shifted single-buffered K/V
// cp.async prefetch (K fetched during softmax+GEMM2, V during GEMM1+softmax).
// B=2,H=8,S=4096,d=64. 512 threads = 16 warps; warp = (head h=w>>1, s-half of 32).

namespace {
constexpr int NH = 8, SEQ = 4096, D = 64;
constexpr int S_TILE = 64, T_TILE = 32;
constexpr int THREADS = 512;
constexpr float SCALE = 0.044194173824159216f;   // 1/sqrt(512)

constexpr int KS_ROW = 80;    // Ks[h][k:64][t:32 f16=64B], pad 80  (conflict-free, 16B mult)
constexpr int VS_ROW = 144;   // Vs[h][t:32][dv:64 f16=128B], pad 144
constexpr int QS_ROW = 144;   // Qs[h][s:64][k:64 f16=128B], pad 144
constexpr int EW_ROW = 80;    // EW[h][s:64][t:32 f16=64B], pad 80

constexpr int KS_H = 64 * KS_ROW;     // 5120
constexpr int VS_H = 32 * VS_ROW;     // 4608
constexpr int QS_H = 64 * QS_ROW;     // 9216
constexpr int EW_H = 64 * EW_ROW;     // 5120

constexpr int SM_K  = 0;                     // 40960
constexpr int SM_V  = NH * KS_H;             // 40960 + 36864
constexpr int SM_Q  = SM_V + NH * VS_H;      // 77824 + 73728
constexpr int SM_EW = SM_Q + NH * QS_H;      // 151552 + 40960
constexpr int SMEM_BYTES = SM_EW + NH * EW_H;  // 192512

constexpr int KV_ELEMS = 2 * NH * D * SEQ;   // per tensor
}

static __device__ __align__(16) __half g_K16[KV_ELEMS];
static __device__ __align__(16) __half g_V16[KV_ELEMS];

__global__ __launch_bounds__(256) void cvt_kv_kernel(const float* __restrict__ K,
                                                     const float* __restrict__ V) {
    const int i = (blockIdx.x * 256 + threadIdx.x) * 8;
    {
        float4 a = *(const float4*)(K + i);
        float4 b = *(const float4*)(K + i + 4);
        __half2 p[4] = { __floats2half2_rn(a.x, a.y), __floats2half2_rn(a.z, a.w),
                         __floats2half2_rn(b.x, b.y), __floats2half2_rn(b.z, b.w) };
        *(uint4*)&g_K16[i] = *(const uint4*)p;
    }
    {
        float4 a = *(const float4*)(V + i);
        float4 b = *(const float4*)(V + i + 4);
        __half2 p[4] = { __floats2half2_rn(a.x, a.y), __floats2half2_rn(a.z, a.w),
                         __floats2half2_rn(b.x, b.y), __floats2half2_rn(b.z, b.w) };
        *(uint4*)&g_V16[i] = *(const uint4*)p;
    }
}

static __device__ __forceinline__ uint32_t smem_u32(const void* p) {
    uint32_t a;
    asm("{ .reg .u64 t; cvta.to.shared.u64 t, %1; cvt.u32.u64 %0, t; }" : "=r"(a) : "l"(p));
    return a;
}
static __device__ __forceinline__ void cp16(uint32_t dst, const void* src) {
    asm volatile("cp.async.cg.shared.global [%0], [%1], 16;" :: "r"(dst), "l"(src));
}
static __device__ __forceinline__ void cp_commit() {
    asm volatile("cp.async.commit_group;" ::: "memory");
}
static __device__ __forceinline__ void cp_wait1() {
    asm volatile("cp.async.wait_group 1;" ::: "memory");
}
static __device__ __forceinline__ void ldsm_x4(uint32_t* r, uint32_t a) {
    asm volatile("ldmatrix.sync.aligned.m8n8.x4.shared.b16 {%0,%1,%2,%3}, [%4];"
        : "=r"(r[0]), "=r"(r[1]), "=r"(r[2]), "=r"(r[3]) : "r"(a));
}
static __device__ __forceinline__ void ldsm_x2t(uint32_t* r, uint32_t a) {
    asm volatile("ldmatrix.sync.aligned.m8n8.x2.trans.shared.b16 {%0,%1}, [%2];"
        : "=r"(r[0]), "=r"(r[1]) : "r"(a));
}
static __device__ __forceinline__ void mma16816(float* c, const uint32_t* a, const uint32_t* b) {
    asm volatile("mma.sync.aligned.m16n8k16.row.col.f32.f16.f16.f32 "
        "{%0,%1,%2,%3}, {%4,%5,%6,%7}, {%8,%9}, {%0,%1,%2,%3};"
        : "+f"(c[0]), "+f"(c[1]), "+f"(c[2]), "+f"(c[3])
        : "r"(a[0]), "r"(a[1]), "r"(a[2]), "r"(a[3]), "r"(b[0]), "r"(b[1]));
}
static __device__ __forceinline__ uint32_t packh2(float x, float y) {
    __half2 h = __floats2half2_rn(x, y);
    return *(const uint32_t*)&h;
}

__global__ __launch_bounds__(THREADS, 1)
void attn_hmma_kernel(const float* __restrict__ Q, float* __restrict__ O)
{
    extern __shared__ char smem[];
    const uint32_t sb = smem_u32(smem);
    const int tid  = threadIdx.x;
    const int wid  = tid >> 5, lane = tid & 31;
    const int b    = blockIdx.x >> 6;
    const int s0   = (blockIdx.x & 63) * S_TILE;
    const int h    = wid >> 1;            // warp's head
    const int half = wid & 1;             // warp's 32-row s-half (2 m-tiles)

    const size_t kv16 = (size_t)b * NH * D * SEQ;

    auto prefetch_K = [&](int t0) {
        const uint32_t kdst = sb + SM_K;
        #pragma unroll
        for (int i = 0; i < 4; ++i) {
            const int f = tid + i * THREADS;           // 0..2047
            const int kh = f >> 8, rem = f & 255;
            const int k = rem >> 2, ts = (rem & 3) * 8;
            cp16(kdst + kh * KS_H + k * KS_ROW + ts * 2,
                 g_K16 + kv16 + (size_t)(kh * D + k) * SEQ + t0 + ts);
        }
    };
    auto prefetch_V = [&](int t0) {
        const uint32_t vdst = sb + SM_V;
        #pragma unroll
        for (int i = 0; i < 4; ++i) {
            const int f = tid + i * THREADS;
            const int vh = f >> 8, rem = f & 255;
            const int t = rem >> 3, ds = (rem & 7) * 8;
            cp16(vdst + vh * VS_H + t * VS_ROW + ds * 2,
                 g_V16 + kv16 + ((size_t)vh * SEQ + t0 + t) * D + ds);
        }
    };

    // ---- prologue: stage Q (scaled f16) + first K/V tiles ----
    #pragma unroll
    for (int i = 0; i < 8; ++i) {
        const int f = tid + i * THREADS;               // 0..4095
        const int qh = f >> 9, rem = f & 511;
        const int s = rem >> 3, kseg = (rem & 7) * 8;
        const float* src = Q + (((size_t)(b * NH + qh)) * SEQ + (s0 + s)) * D + kseg;
        float4 v0 = *(const float4*)src;
        float4 v1 = *(const float4*)(src + 4);
        uint32_t p[4] = { packh2(v0.x * SCALE, v0.y * SCALE), packh2(v0.z * SCALE, v0.w * SCALE),
                          packh2(v1.x * SCALE, v1.y * SCALE), packh2(v1.z * SCALE, v1.w * SCALE) };
        *(uint4*)(smem + SM_Q + qh * QS_H + s * QS_ROW + kseg * 2) = *(const uint4*)p;
    }
    prefetch_K(0); cp_commit();      // group K0
    prefetch_V(0); cp_commit();      // group V0
    cp_wait1();                      // K0 done (V0 may fly)
    __syncthreads();

    float o[2][8][4];                // O accum: [mt][n0][4] = 32s x 64dv per warp
    #pragma unroll
    for (int mt = 0; mt < 2; ++mt)
        #pragma unroll
        for (int n = 0; n < 8; ++n)
            #pragma unroll
            for (int i = 0; i < 4; ++i) o[mt][n][i] = 0.f;

    const uint32_t qb = sb + SM_Q + h * QS_H + (half * 32 + (lane & 15)) * QS_ROW
                      + (lane >> 4) * 16;
    const uint32_t kb = sb + SM_K + h * KS_H + (lane & 15) * KS_ROW;
    const uint32_t wb = sb + SM_EW + h * EW_H + (half * 32 + (lane & 15)) * EW_ROW
                      + (lane >> 4) * 16;
    const uint32_t vb = sb + SM_V + h * VS_H + (lane & 15) * VS_ROW;

    for (int t0g = 0; t0g < SEQ; t0g += T_TILE) {
        // ---- GEMM1: E[32s x 32t] = Qh @ K ; B-frags shared across 2 m-tiles ----
        float c1[2][4][4];
        #pragma unroll
        for (int mt = 0; mt < 2; ++mt)
            #pragma unroll
            for (int n = 0; n < 4; ++n)
                #pragma unroll
                for (int i = 0; i < 4; ++i) c1[mt][n][i] = 0.f;
        #pragma unroll
        for (int k0 = 0; k0 < 4; ++k0) {
            uint32_t a0[4], a1[4];
            ldsm_x4(a0, qb + k0 * 32);
            ldsm_x4(a1, qb + 16 * QS_ROW + k0 * 32);
            #pragma unroll
            for (int n0 = 0; n0 < 4; ++n0) {
                uint32_t bf[2];
                ldsm_x2t(bf, kb + k0 * 16 * KS_ROW + n0 * 16);
                mma16816(c1[0][n0], a0, bf);
                mma16816(c1[1][n0], a1, bf);
            }
        }
        // ---- E -> f16 exchange ----
        {
            char* ebase = smem + SM_EW + h * EW_H;
            const int cb = (lane & 3) * 4;
            #pragma unroll
            for (int mt = 0; mt < 2; ++mt) {
                const int r0 = half * 32 + mt * 16 + (lane >> 2);
                #pragma unroll
                for (int n0 = 0; n0 < 4; ++n0) {
                    *(uint32_t*)(ebase + r0 * EW_ROW + n0 * 16 + cb) =
                        packh2(c1[mt][n0][0], c1[mt][n0][1]);
                    *(uint32_t*)(ebase + (r0 + 8) * EW_ROW + n0 * 16 + cb) =
                        packh2(c1[mt][n0][2], c1[mt][n0][3]);
                }
            }
        }
        __syncthreads();                       // #1: E visible, K region free
        if (t0g + T_TILE < SEQ) prefetch_K(t0g + T_TILE);
        cp_commit();                           // group K(i+1)

        // ---- softmax over 8 heads, in place (thread-exclusive) ----
        {
            const int s = tid >> 3, tp = tid & 7;
            #pragma unroll
            for (int c2 = 0; c2 < 2; ++c2) {
                const int off = s * EW_ROW + tp * 8 + c2 * 4;
                float ex[16];
                float sum0 = 0.f, sum1 = 0.f;
                #pragma unroll
                for (int hh = 0; hh < 8; ++hh) {
                    __half2 hv = *(const __half2*)(smem + SM_EW + hh * EW_H + off);
                    float2 f = __half22float2(hv);
                    ex[2 * hh]     = __expf(f.x);
                    ex[2 * hh + 1] = __expf(f.y);
                    sum0 += ex[2 * hh];
                    sum1 += ex[2 * hh + 1];
                }
                const float r0 = __fdividef(1.f, sum0);
                const float r1 = __fdividef(1.f, sum1);
                #pragma unroll
                for (int hh = 0; hh < 8; ++hh)
                    *(uint32_t*)(smem + SM_EW + hh * EW_H + off) =
                        packh2(ex[2 * hh] * r0, ex[2 * hh + 1] * r1);
            }
        }
        cp_wait1();                            // V(i) done
        __syncthreads();                       // #2: W visible, V visible

        // ---- GEMM2: O += W[32s x 32t] @ V[32t x 64dv] ; B-frags shared ----
        {
            uint32_t a2[2][2][4];
            #pragma unroll
            for (int mt = 0; mt < 2; ++mt)
                #pragma unroll
                for (int k0 = 0; k0 < 2; ++k0)
                    ldsm_x4(a2[mt][k0], wb + mt * 16 * EW_ROW + k0 * 32);
            #pragma unroll
            for (int n0 = 0; n0 < 8; ++n0) {
                #pragma unroll
                for (int k0 = 0; k0 < 2; ++k0) {
                    uint32_t bf[2];
                    ldsm_x2t(bf, vb + k0 * 16 * VS_ROW + n0 * 16);
                    mma16816(o[0][n0], a2[0][k0], bf);
                    mma16816(o[1][n0], a2[1][k0], bf);
                }
            }
        }
        __syncthreads();                       // #3: V region free, W consumed
        if (t0g + T_TILE < SEQ) prefetch_V(t0g + T_TILE);
        cp_commit();                           // group V(i+1)
        cp_wait1();                            // K(i+1) done
        __syncthreads();                       // #4: K visible
    }

    // ---- writeback: raw [B,H,S,64] order ----
    {
        const int c = (lane & 3) * 2;
        #pragma unroll
        for (int mt = 0; mt < 2; ++mt) {
            const int r = half * 32 + mt * 16 + (lane >> 2);
            float* dst = O + (((size_t)(b * NH + h)) * SEQ + (s0 + r)) * D;
            #pragma unroll
            for (int n0 = 0; n0 < 8; ++n0) {
                *(float2*)(dst + n0 * 8 + c)         = make_float2(o[mt][n0][0], o[mt][n0][1]);
                *(float2*)(dst + 8 * D + n0 * 8 + c) = make_float2(o[mt][n0][2], o[mt][n0][3]);
            }
        }
    }
}

extern "C" void kernel_launch(void* const* d_in, const int* in_sizes, int n_in,
                              void* d_out, int out_size) {
    (void)in_sizes; (void)n_in; (void)out_size;
    const float* Q = (const float*)d_in[0];
    const float* K = (const float*)d_in[1];
    const float* V = (const float*)d_in[2];
    float* O = (float*)d_out;
    cvt_kv_kernel<<<KV_ELEMS / 8 / 256, 256>>>(K, V);
    cudaFuncSetAttribute(attn_hmma_kernel,
                         cudaFuncAttributeMaxDynamicSharedMemorySize, SMEM_BYTES);
    attn_hmma_kernel<<<2 * (SEQ / S_TILE), THREADS, SMEM_BYTES>>>(Q, O);
}

// round 14
// speedup vs baseline: 7.0776x; 1.0494x over previous
#include <cuda_runtime.h>
#include <cuda_fp16.h>
#include <cstdint>

// Head-axis-softmax attention, HMMA fp16/f32. R14:
//  - swizzled smem (SW128/SW64, zero padding except E/W exchange)
//  - V double-buffered (full-iteration prefetch lead), K phase-shifted
//  - 3 barriers + 1 wait_group per tile
//  - pre-pass converts Q (scale folded), K, V to f16; main kernel is pure cp.async
// B=2,H=8,S=4096,d=64. Grid 128 = b x 64 s-blocks of 64. 512 threads = 16 warps;
// warp = (head h=w>>1, 32-row s-half = w&1, 2 m-tiles each).

namespace {
constexpr int NH = 8, SEQ = 4096, D = 64;
constexpr int S_TILE = 64, T_TILE = 32;
constexpr int THREADS = 512;
constexpr float SCALE = 0.044194173824159216f;   // 1/sqrt(512)

// smem regions (bytes)
constexpr int KS_H = 64 * 64;        // K: per head 64 k-rows x 64B (32 t f16), SW64
constexpr int VS_H = 32 * 128;       // V: per head 32 t-rows x 128B (64 dv f16), SW128
constexpr int QS_H = 64 * 128;       // Q: per head 64 s-rows x 128B (64 k f16), SW128
constexpr int EW_ROW = 80;           // E/W exchange: padded rows (conflict-free, R13-verified)
constexpr int EW_H = 64 * EW_ROW;

constexpr int SM_K  = 0;                      // 32768
constexpr int SM_V  = NH * KS_H;              // 32768 .. +65536 (2 buffers)
constexpr int SM_Q  = SM_V + 2 * NH * VS_H;   // 98304 .. +65536
constexpr int SM_EW = SM_Q + NH * QS_H;       // 163840 .. +40960
constexpr int SMEM_BYTES = SM_EW + NH * EW_H; // 204800

constexpr int KV_ELEMS = 2 * NH * D * SEQ;    // elements per tensor
}

static __device__ __align__(16) __half g_Q16[KV_ELEMS];   // pre-scaled
static __device__ __align__(16) __half g_K16[KV_ELEMS];
static __device__ __align__(16) __half g_V16[KV_ELEMS];

__global__ __launch_bounds__(256) void cvt_qkv_kernel(const float* __restrict__ Q,
                                                      const float* __restrict__ K,
                                                      const float* __restrict__ V) {
    const int i = (blockIdx.x * 256 + threadIdx.x) * 8;
    {
        float4 a = *(const float4*)(Q + i);
        float4 b = *(const float4*)(Q + i + 4);
        __half2 p[4] = { __floats2half2_rn(a.x * SCALE, a.y * SCALE),
                         __floats2half2_rn(a.z * SCALE, a.w * SCALE),
                         __floats2half2_rn(b.x * SCALE, b.y * SCALE),
                         __floats2half2_rn(b.z * SCALE, b.w * SCALE) };
        *(uint4*)&g_Q16[i] = *(const uint4*)p;
    }
    {
        float4 a = *(const float4*)(K + i);
        float4 b = *(const float4*)(K + i + 4);
        __half2 p[4] = { __floats2half2_rn(a.x, a.y), __floats2half2_rn(a.z, a.w),
                         __floats2half2_rn(b.x, b.y), __floats2half2_rn(b.z, b.w) };
        *(uint4*)&g_K16[i] = *(const uint4*)p;
    }
    {
        float4 a = *(const float4*)(V + i);
        float4 b = *(const float4*)(V + i + 4);
        __half2 p[4] = { __floats2half2_rn(a.x, a.y), __floats2half2_rn(a.z, a.w),
                         __floats2half2_rn(b.x, b.y), __floats2half2_rn(b.z, b.w) };
        *(uint4*)&g_V16[i] = *(const uint4*)p;
    }
}

static __device__ __forceinline__ uint32_t smem_u32(const void* p) {
    uint32_t a;
    asm("{ .reg .u64 t; cvta.to.shared.u64 t, %1; cvt.u32.u64 %0, t; }" : "=r"(a) : "l"(p));
    return a;
}
static __device__ __forceinline__ void cp16(uint32_t dst, const void* src) {
    asm volatile("cp.async.cg.shared.global [%0], [%1], 16;" :: "r"(dst), "l"(src));
}
static __device__ __forceinline__ void cp_commit() {
    asm volatile("cp.async.commit_group;" ::: "memory");
}
static __device__ __forceinline__ void cp_wait0() {
    asm volatile("cp.async.wait_group 0;" ::: "memory");
}
static __device__ __forceinline__ void ldsm_x4(uint32_t* r, uint32_t a) {
    asm volatile("ldmatrix.sync.aligned.m8n8.x4.shared.b16 {%0,%1,%2,%3}, [%4];"
        : "=r"(r[0]), "=r"(r[1]), "=r"(r[2]), "=r"(r[3]) : "r"(a));
}
static __device__ __forceinline__ void ldsm_x2t(uint32_t* r, uint32_t a) {
    asm volatile("ldmatrix.sync.aligned.m8n8.x2.trans.shared.b16 {%0,%1}, [%2];"
        : "=r"(r[0]), "=r"(r[1]) : "r"(a));
}
static __device__ __forceinline__ void mma16816(float* c, const uint32_t* a, const uint32_t* b) {
    asm volatile("mma.sync.aligned.m16n8k16.row.col.f32.f16.f16.f32 "
        "{%0,%1,%2,%3}, {%4,%5,%6,%7}, {%8,%9}, {%0,%1,%2,%3};"
        : "+f"(c[0]), "+f"(c[1]), "+f"(c[2]), "+f"(c[3])
        : "r"(a[0]), "r"(a[1]), "r"(a[2]), "r"(a[3]), "r"(b[0]), "r"(b[1]));
}
static __device__ __forceinline__ uint32_t packh2(float x, float y) {
    __half2 h = __floats2half2_rn(x, y);
    return *(const uint32_t*)&h;
}

__global__ __launch_bounds__(THREADS, 1)
void attn_hmma_kernel(float* __restrict__ O)
{
    extern __shared__ char smem[];
    const uint32_t sb = smem_u32(smem);
    const int tid  = threadIdx.x;
    const int wid  = tid >> 5, lane = tid & 31;
    const int b    = blockIdx.x >> 6;
    const int s0   = (blockIdx.x & 63) * S_TILE;
    const int h    = wid >> 1;
    const int half = wid & 1;

    const size_t kv16 = (size_t)b * NH * D * SEQ;

    auto prefetch_K = [&](int t0) {
        #pragma unroll
        for (int i = 0; i < 4; ++i) {
            const int f = tid + i * THREADS;           // 0..2047 16B chunks
            const int kh = f >> 8, rem = f & 255;
            const int k = rem >> 2, tc = rem & 3;      // row k, t-chunk
            cp16(sb + SM_K + kh * KS_H + k * 64 + (((tc ^ (k & 3))) << 4),
                 g_K16 + kv16 + (size_t)(kh * D + k) * SEQ + t0 + tc * 8);
        }
    };
    auto prefetch_V = [&](int t0, int buf) {
        const uint32_t vdst = sb + SM_V + buf * (NH * VS_H);
        #pragma unroll
        for (int i = 0; i < 4; ++i) {
            const int f = tid + i * THREADS;
            const int vh = f >> 8, rem = f & 255;
            const int t = rem >> 3, dc = rem & 7;      // row t, dv-chunk
            cp16(vdst + vh * VS_H + t * 128 + ((dc ^ (t & 7)) << 4),
                 g_V16 + kv16 + ((size_t)vh * SEQ + t0 + t) * D + dc * 8);
        }
    };

    // ---- prologue: cp.async Q (swizzled) + K0 + V0 (group0), V1 (group1) ----
    #pragma unroll
    for (int i = 0; i < 8; ++i) {
        const int f = tid + i * THREADS;               // 0..4095 16B chunks
        const int qh = f >> 9, rem = f & 511;
        const int s = rem >> 3, kc = rem & 7;
        cp16(sb + SM_Q + qh * QS_H + s * 128 + ((kc ^ (s & 7)) << 4),
             g_Q16 + kv16 + ((size_t)(qh) * SEQ + s0 + s) * D + kc * 8);
    }
    prefetch_K(0);
    prefetch_V(0, 0);
    cp_commit();                 // group: Q + K0 + V0
    prefetch_V(T_TILE, 1);
    cp_commit();                 // group: V1
    cp_wait0();
    __syncthreads();

    float o[2][8][4];
    #pragma unroll
    for (int mt = 0; mt < 2; ++mt)
        #pragma unroll
        for (int n = 0; n < 8; ++n)
            #pragma unroll
            for (int i = 0; i < 4; ++i) o[mt][n][i] = 0.f;

    // per-warp bases (swizzle xors are lane-constant)
    const uint32_t qb0 = sb + SM_Q + h * QS_H + (half * 32 + (lane & 15)) * 128;
    const int      qx  = lane & 7;                 // row&7 == lane&7 for all m-tiles
    const uint32_t kb0 = sb + SM_K + h * KS_H + (lane & 15) * 64;
    const int      kx  = lane & 3;
    const uint32_t vb0r = h * VS_H + (lane & 15) * 128;
    const int      vx  = lane & 7;
    const uint32_t wb  = sb + SM_EW + h * EW_H + (half * 32 + (lane & 15)) * EW_ROW
                       + (lane >> 4) * 16;

    for (int t0g = 0; t0g < SEQ; t0g += T_TILE) {
        const int buf = (t0g >> 5) & 1;

        // ---- GEMM1: E[32s x 32t] = Qh @ K ; B-frags shared across 2 m-tiles ----
        float c1[2][4][4];
        #pragma unroll
        for (int mt = 0; mt < 2; ++mt)
            #pragma unroll
            for (int n = 0; n < 4; ++n)
                #pragma unroll
                for (int i = 0; i < 4; ++i) c1[mt][n][i] = 0.f;
        #pragma unroll
        for (int k0 = 0; k0 < 4; ++k0) {
            uint32_t a0[4], a1[4];
            const uint32_t qc = (uint32_t)((((lane >> 4) + 2 * k0) ^ qx) << 4);
            ldsm_x4(a0, qb0 + qc);
            ldsm_x4(a1, qb0 + 16 * 128 + qc);
            #pragma unroll
            for (int n0 = 0; n0 < 4; ++n0) {
                uint32_t bf[2];
                ldsm_x2t(bf, kb0 + k0 * 16 * 64 + ((n0 ^ kx) << 4));
                mma16816(c1[0][n0], a0, bf);
                mma16816(c1[1][n0], a1, bf);
            }
        }
        // ---- E -> f16 exchange (padded EW region) ----
        {
            char* ebase = smem + SM_EW + h * EW_H;
            const int cb = (lane & 3) * 4;
            #pragma unroll
            for (int mt = 0; mt < 2; ++mt) {
                const int r0 = half * 32 + mt * 16 + (lane >> 2);
                #pragma unroll
                for (int n0 = 0; n0 < 4; ++n0) {
                    *(uint32_t*)(ebase + r0 * EW_ROW + n0 * 16 + cb) =
                        packh2(c1[mt][n0][0], c1[mt][n0][1]);
                    *(uint32_t*)(ebase + (r0 + 8) * EW_ROW + n0 * 16 + cb) =
                        packh2(c1[mt][n0][2], c1[mt][n0][3]);
                }
            }
        }
        __syncthreads();                       // #1: E visible, K reads done
        if (t0g + T_TILE < SEQ) prefetch_K(t0g + T_TILE);
        cp_commit();                           // group K(i+1)

        // ---- softmax over 8 heads, in place, 8B vectors (4 t per thread) ----
        {
            const int s = tid >> 3, tq = tid & 7;
            const int off = s * EW_ROW + tq * 8;
            float ex[8][4];
            float sum0 = 0.f, sum1 = 0.f, sum2 = 0.f, sum3 = 0.f;
            #pragma unroll
            for (int hh = 0; hh < 8; ++hh) {
                uint2 v = *(const uint2*)(smem + SM_EW + hh * EW_H + off);
                float2 fa = __half22float2(*(const __half2*)&v.x);
                float2 fb = __half22float2(*(const __half2*)&v.y);
                ex[hh][0] = __expf(fa.x); ex[hh][1] = __expf(fa.y);
                ex[hh][2] = __expf(fb.x); ex[hh][3] = __expf(fb.y);
                sum0 += ex[hh][0]; sum1 += ex[hh][1];
                sum2 += ex[hh][2]; sum3 += ex[hh][3];
            }
            const float r0 = __fdividef(1.f, sum0);
            const float r1 = __fdividef(1.f, sum1);
            const float r2 = __fdividef(1.f, sum2);
            const float r3 = __fdividef(1.f, sum3);
            #pragma unroll
            for (int hh = 0; hh < 8; ++hh) {
                uint2 w;
                w.x = packh2(ex[hh][0] * r0, ex[hh][1] * r1);
                w.y = packh2(ex[hh][2] * r2, ex[hh][3] * r3);
                *(uint2*)(smem + SM_EW + hh * EW_H + off) = w;
            }
        }
        __syncthreads();                       // #2: W visible

        // ---- GEMM2: O += W[32s x 32t] @ V[32t x 64dv] ; B-frags shared ----
        {
            const uint32_t vb = sb + SM_V + buf * (NH * VS_H) + vb0r;
            uint32_t a2[2][2][4];
            #pragma unroll
            for (int mt = 0; mt < 2; ++mt)
                #pragma unroll
                for (int k0 = 0; k0 < 2; ++k0)
                    ldsm_x4(a2[mt][k0], wb + mt * 16 * EW_ROW + k0 * 32);
            #pragma unroll
            for (int n0 = 0; n0 < 8; ++n0) {
                #pragma unroll
                for (int k0 = 0; k0 < 2; ++k0) {
                    uint32_t bf[2];
                    ldsm_x2t(bf, vb + k0 * 16 * 128 + ((n0 ^ vx) << 4));
                    mma16816(o[0][n0], a2[0][k0], bf);
                    mma16816(o[1][n0], a2[1][k0], bf);
                }
            }
        }
        cp_wait0();                            // K(i+1) and V(i+1) resident
        __syncthreads();                       // #3: all GEMM2 done; staged data visible
        if (t0g + 2 * T_TILE < SEQ) prefetch_V(t0g + 2 * T_TILE, buf);
        cp_commit();                           // group V(i+2) into freed buffer
    }

    // ---- writeback: raw [B,H,S,64] order ----
    {
        const int c = (lane & 3) * 2;
        #pragma unroll
        for (int mt = 0; mt < 2; ++mt) {
            const int r = half * 32 + mt * 16 + (lane >> 2);
            float* dst = O + (((size_t)(b * NH + h)) * SEQ + (s0 + r)) * D;
            #pragma unroll
            for (int n0 = 0; n0 < 8; ++n0) {
                *(float2*)(dst + n0 * 8 + c)         = make_float2(o[mt][n0][0], o[mt][n0][1]);
                *(float2*)(dst + 8 * D + n0 * 8 + c) = make_float2(o[mt][n0][2], o[mt][n0][3]);
            }
        }
    }
}

extern "C" void kernel_launch(void* const* d_in, const int* in_sizes, int n_in,
                              void* d_out, int out_size) {
    (void)in_sizes; (void)n_in; (void)out_size;
    const float* Q = (const float*)d_in[0];
    const float* K = (const float*)d_in[1];
    const float* V = (const float*)d_in[2];
    float* O = (float*)d_out;
    cvt_qkv_kernel<<<KV_ELEMS / 8 / 256, 256>>>(Q, K, V);
    cudaFuncSetAttribute(attn_hmma_kernel,
                         cudaFuncAttributeMaxDynamicSharedMemorySize, SMEM_BYTES);
    attn_hmma_kernel<<<2 * (SEQ / S_TILE), THREADS, SMEM_BYTES>>>(O);
}